// round 15
// baseline (speedup 1.0000x reference)
#include <cuda_runtime.h>
#include <math.h>

// Problem constants
#define TOK    4096          // B*S = 2*2048
#define SLEN   2048
#define NHEAD  32
#define HD     80
#define HID    2560          // NHEAD*HD
#define HID3   7680
#define HID4   10240
#define ROT_HALF 16
#define HGRP   8             // heads per scores buffer group

// ---------------- scratch (device globals; no allocation allowed) ----------
__device__ float g_ln  [TOK * HID];
__device__ float g_qkv [TOK * HID3];
__device__ float g_attn[TOK * HID];
__device__ float g_fc1 [TOK * HID4];
__device__ float g_q   [TOK * HID];
__device__ float g_k   [TOK * HID];
__device__ float g_sc  [(long)HGRP * SLEN * SLEN];
__device__ float g_cos [SLEN * ROT_HALF];
__device__ float g_sin [SLEN * ROT_HALF];

// ---------------------------------------------------------------- GELU
__device__ __forceinline__ float fast_gelu(float x)
{
    const float c = 0.7978845608028654f;   // sqrt(2/pi)
    float inner = c * (x + 0.044715f * x * x * x);
    return 0.5f * x * (1.0f + tanhf(inner));
}

// ---------------------------------------------------------------- LayerNorm
__global__ __launch_bounds__(256) void ln_simple_kernel(
    const float* __restrict__ x, const float* __restrict__ w,
    const float* __restrict__ b, float* __restrict__ out)
{
    const int t    = blockIdx.x * 8 + (threadIdx.x >> 5);
    const int lane = threadIdx.x & 31;
    const float* xp = x + (long)t * HID;

    float s = 0.f, q = 0.f;
    for (int i = lane; i < HID; i += 32) {
        float v = xp[i];
        s += v; q += v * v;
    }
    #pragma unroll
    for (int m = 16; m > 0; m >>= 1) {
        s += __shfl_xor_sync(0xffffffffu, s, m);
        q += __shfl_xor_sync(0xffffffffu, q, m);
    }
    const float mu   = s / (float)HID;
    const float var  = q / (float)HID - mu * mu;
    const float rstd = rsqrtf(var + 1e-5f);

    float* op = out + (long)t * HID;
    for (int i = lane; i < HID; i += 32)
        op[i] = (xp[i] - mu) * rstd * w[i] + b[i];
}

// ---------------------------------------------------------------- GEMM (textbook)
template<bool GELU, bool RESID>
__global__ __launch_bounds__(1024) void gemm32_kernel(
    const float* __restrict__ A, const float* __restrict__ W,
    const float* __restrict__ bias, const float* __restrict__ R,
    float* __restrict__ C, int M, int N, int K)
{
    __shared__ float As[32][33];
    __shared__ float Bs[32][33];

    const int tx  = threadIdx.x;
    const int ty  = threadIdx.y;
    const int row = blockIdx.y * 32 + ty;
    const int col = blockIdx.x * 32 + tx;

    float acc = 0.f;
    for (int t = 0; t < K; t += 32) {
        As[ty][tx] = A[(long)row * K + t + tx];
        Bs[ty][tx] = W[(long)(t + ty) * N + col];
        __syncthreads();
        #pragma unroll
        for (int k = 0; k < 32; k++)
            acc = fmaf(As[ty][k], Bs[k][tx], acc);
        __syncthreads();
    }

    float r = acc + bias[col];
    if (RESID) r += R[(long)row * N + col];
    if (GELU)  r = fast_gelu(r);
    C[(long)row * N + col] = r;
}

// ---------------------------------------------------------------- RoPE table
// ROUND 14 EXPERIMENT: CONJUGATE rotation — sin table negated. With this,
// rot1 = x1*c + x2*s and rot2 = -x1*s + x2*c (rotation by -m*theta), the
// classic sign-convention alternative. Only change vs round 11.
__global__ __launch_bounds__(256) void rope_table_kernel()
{
    const int i = blockIdx.x * 256 + threadIdx.x;   // 0 .. SLEN*16-1
    const int s = i >> 4;
    const int d = i & 15;
    const float inv = 1.0f / powf(10000.0f, (float)d * 2.0f / 32.0f);
    float cs, sn;
    sincosf((float)s * inv, &cs, &sn);
    g_cos[i] = cs;
    g_sin[i] = -sn;          // <<< EXPERIMENT: conjugate (was +sn)
}

// ---------------------------------------------------------------- RoPE apply (literal)
__global__ __launch_bounds__(256) void rope_apply_kernel(
    const float* __restrict__ qkv, float* __restrict__ Q, float* __restrict__ K)
{
    const long i = (long)blockIdx.x * 256 + threadIdx.x;   // 0 .. TOK*HID
    const int  t = (int)(i / HID);
    const int  c = (int)(i % HID);
    const int  h = c / HD;
    const int  d = c % HD;
    const int  s = t % SLEN;

    const float* qp = qkv + (long)t * HID3 + h * HD;
    const float* kp = qp + HID;

    float qv, kv;
    if (d < ROT_HALF) {
        const float cs = g_cos[s * ROT_HALF + d];
        const float sn = g_sin[s * ROT_HALF + d];
        qv = qp[d] * cs - qp[d + ROT_HALF] * sn;
        kv = kp[d] * cs - kp[d + ROT_HALF] * sn;
    } else if (d < 2 * ROT_HALF) {
        const int dd = d - ROT_HALF;
        const float cs = g_cos[s * ROT_HALF + dd];
        const float sn = g_sin[s * ROT_HALF + dd];
        qv = qp[dd] * sn + qp[d] * cs;
        kv = kp[dd] * sn + kp[d] * cs;
    } else {
        qv = qp[d];
        kv = kp[d];
    }
    Q[i] = qv;
    K[i] = kv;
}

// ---------------------------------------------------------------- Dense scores
__global__ __launch_bounds__(256) void scores_kernel(
    const float* __restrict__ Q, const float* __restrict__ K,
    float* __restrict__ SC, int b, int hg)
{
    const int q  = blockIdx.x * 16 + threadIdx.x;
    const int k  = blockIdx.y * 16 + threadIdx.y;
    const int hh = blockIdx.z;
    if (k > q) return;
    const int h = hg * HGRP + hh;
    const float scale = 0.11180339887498948f;   // 1/sqrt(80)

    const float* qp = Q + (long)(b * SLEN + q) * HID + h * HD;
    const float* kp = K + (long)(b * SLEN + k) * HID + h * HD;
    float s = 0.f;
    #pragma unroll 8
    for (int d = 0; d < HD; d++)
        s = fmaf(qp[d], kp[d], s);
    SC[((long)hh * SLEN + q) * SLEN + k] = s * scale;
}

// ---------------------------------------------------------------- Dense softmax
__global__ __launch_bounds__(256) void softmax_kernel(float* __restrict__ SC)
{
    const int q    = blockIdx.x * 8 + (threadIdx.x >> 5);
    const int hh   = blockIdx.y;
    const int lane = threadIdx.x & 31;
    float* row = SC + ((long)hh * SLEN + q) * SLEN;
    const int n = q + 1;

    float mx = -1e30f;
    for (int i = lane; i < n; i += 32) mx = fmaxf(mx, row[i]);
    #pragma unroll
    for (int m = 16; m > 0; m >>= 1)
        mx = fmaxf(mx, __shfl_xor_sync(0xffffffffu, mx, m));

    float sum = 0.f;
    for (int i = lane; i < n; i += 32) {
        const float e = __expf(row[i] - mx);
        row[i] = e;
        sum += e;
    }
    #pragma unroll
    for (int m = 16; m > 0; m >>= 1)
        sum += __shfl_xor_sync(0xffffffffu, sum, m);

    const float inv = 1.0f / sum;
    for (int i = lane; i < n; i += 32) row[i] *= inv;
}

// ---------------------------------------------------------------- Dense P@V
__global__ __launch_bounds__(80) void pv_kernel(
    const float* __restrict__ SC, const float* __restrict__ qkv,
    float* __restrict__ attn, int b, int hg)
{
    const int q  = blockIdx.x;
    const int hh = blockIdx.y;
    const int h  = hg * HGRP + hh;
    const int d  = threadIdx.x;

    const float* P = SC + ((long)hh * SLEN + q) * SLEN;
    const float* V = qkv + (long)(b * SLEN) * HID3 + 2 * HID + h * HD + d;

    float acc = 0.f;
    for (int k = 0; k <= q; k++)
        acc = fmaf(P[k], V[(long)k * HID3], acc);

    attn[(long)(b * SLEN + q) * HID + h * HD + d] = acc;
}

// ---------------------------------------------------------------- launch
// Established by measurement: dict-order inputs (R10 sizes + R12 arithmetic);
// out_weight normal orientation (R10); non-attention half correct (R13
// ablation = pure A_ref-term); defect INSIDE attention with norm ratio 0.90,
// rho 0.82 -> rope-convention candidates. R14 tests CONJUGATE rotation.
extern "C" void kernel_launch(void* const* d_in, const int* in_sizes, int n_in,
                              void* d_out, int out_size)
{
    (void)in_sizes; (void)n_in; (void)out_size;
    const float* hidden = (const float*)d_in[0];
    const float* ln_w   = (const float*)d_in[1];
    const float* ln_b   = (const float*)d_in[2];
    const float* qkv_w  = (const float*)d_in[3];
    const float* qkv_b  = (const float*)d_in[4];
    const float* out_w  = (const float*)d_in[5];
    const float* out_b  = (const float*)d_in[6];
    const float* fc1_w  = (const float*)d_in[7];
    const float* fc1_b  = (const float*)d_in[8];
    const float* fc2_w  = (const float*)d_in[9];
    const float* fc2_b  = (const float*)d_in[10];
    float* out = (float*)d_out;

    float *p_ln, *p_qkv, *p_attn, *p_fc1, *p_q, *p_k, *p_sc;
    cudaGetSymbolAddress((void**)&p_ln,   g_ln);
    cudaGetSymbolAddress((void**)&p_qkv,  g_qkv);
    cudaGetSymbolAddress((void**)&p_attn, g_attn);
    cudaGetSymbolAddress((void**)&p_fc1,  g_fc1);
    cudaGetSymbolAddress((void**)&p_q,    g_q);
    cudaGetSymbolAddress((void**)&p_k,    g_k);
    cudaGetSymbolAddress((void**)&p_sc,   g_sc);

    const dim3 tb(32, 32);

    // 1. LayerNorm
    ln_simple_kernel<<<TOK / 8, 256>>>(hidden, ln_w, ln_b, p_ln);

    // 2. QKV projection
    gemm32_kernel<false, false><<<dim3(HID3 / 32, TOK / 32), tb>>>(
        p_ln, qkv_w, qkv_b, nullptr, p_qkv, TOK, HID3, HID);

    // 3. rope table (CONJUGATE this round) + literal rope application
    rope_table_kernel<<<(SLEN * ROT_HALF) / 256, 256>>>();
    rope_apply_kernel<<<(TOK * HID) / 256, 256>>>(p_qkv, p_q, p_k);

    // 4. DENSE attention, literal reference formula, 8 heads at a time
    for (int b = 0; b < 2; b++) {
        for (int hg = 0; hg < NHEAD / HGRP; hg++) {
            scores_kernel<<<dim3(SLEN / 16, SLEN / 16, HGRP), dim3(16, 16)>>>(
                p_q, p_k, p_sc, b, hg);
            softmax_kernel<<<dim3(SLEN / 8, HGRP), 256>>>(p_sc);
            pv_kernel<<<dim3(SLEN, HGRP), 80>>>(p_sc, p_qkv, p_attn, b, hg);
        }
    }

    // 5. out projection + residual(hidden) -> d_out
    gemm32_kernel<false, true><<<dim3(HID / 32, TOK / 32), tb>>>(
        p_attn, out_w, out_b, hidden, out, TOK, HID, HID);

    // 6. FC1 + GELU
    gemm32_kernel<true, false><<<dim3(HID4 / 32, TOK / 32), tb>>>(
        p_ln, fc1_w, fc1_b, nullptr, p_fc1, TOK, HID4, HID);

    // 7. FC2 + residual(d_out) -> d_out
    gemm32_kernel<false, true><<<dim3(HID / 32, TOK / 32), tb>>>(
        p_fc1, fc2_w, fc2_b, out, out, TOK, HID, HID4);
}

// round 16
// speedup vs baseline: 4.6760x; 4.6760x over previous
#include <cuda_runtime.h>
#include <math.h>

// Problem constants
#define TOK    4096          // B*S = 2*2048
#define SLEN   2048
#define NHEAD  32
#define HD     80
#define HID    2560          // NHEAD*HD
#define HID3   7680
#define HID4   10240
#define ROT_HALF 16

// ---------------- scratch (device globals; no allocation allowed) ----------
__device__ float g_ln  [TOK * HID];
__device__ float g_qkv [TOK * HID3];
__device__ float g_attn[TOK * HID];
__device__ float g_fc1 [TOK * HID4];
__device__ float g_q   [TOK * HID];    // rope'd (conjugate) Q
__device__ float g_k   [TOK * HID];    // rope'd (conjugate) K
__device__ float g_cos [SLEN * ROT_HALF];
__device__ float g_sin [SLEN * ROT_HALF];

// ---------------------------------------------------------------- GELU
__device__ __forceinline__ float fast_gelu(float x)
{
    const float c = 0.7978845608028654f;   // sqrt(2/pi)
    float inner = c * (x + 0.044715f * x * x * x);
    return 0.5f * x * (1.0f + tanhf(inner));
}

// ---------------------------------------------------------------- LayerNorm
__global__ __launch_bounds__(256) void ln_simple_kernel(
    const float* __restrict__ x, const float* __restrict__ w,
    const float* __restrict__ b, float* __restrict__ out)
{
    const int t    = blockIdx.x * 8 + (threadIdx.x >> 5);
    const int lane = threadIdx.x & 31;
    const float* xp = x + (long)t * HID;

    float s = 0.f, q = 0.f;
    for (int i = lane; i < HID; i += 32) {
        float v = xp[i];
        s += v; q += v * v;
    }
    #pragma unroll
    for (int m = 16; m > 0; m >>= 1) {
        s += __shfl_xor_sync(0xffffffffu, s, m);
        q += __shfl_xor_sync(0xffffffffu, q, m);
    }
    const float mu   = s / (float)HID;
    const float var  = q / (float)HID - mu * mu;
    const float rstd = rsqrtf(var + 1e-5f);

    float* op = out + (long)t * HID;
    for (int i = lane; i < HID; i += 32)
        op[i] = (xp[i] - mu) * rstd * w[i] + b[i];
}

// ---------------------------------------------------------------- SGEMM (fast)
// C[M,N] = A[M,K] @ W[K,N] + bias (+ residual) (gelu optional)
// 128x128 block tile, 16 k-tile, 256 threads, 8x8 accumulators per thread.
// Requires M%128==0, N%128==0, K%16==0 (all shapes here satisfy this).
template<bool GELU, bool RESID>
__global__ __launch_bounds__(256) void sgemm_kernel(
    const float* __restrict__ A, const float* __restrict__ W,
    const float* __restrict__ bias, const float* __restrict__ R,
    float* __restrict__ C, int M, int N, int K)
{
    __shared__ float As[16][128];   // As[k][m]  (A staged transposed)
    __shared__ float Bs[16][128];   // Bs[k][n]

    const int tid = threadIdx.x;
    const int bm = blockIdx.y * 128;
    const int bn = blockIdx.x * 128;
    const int tr = (tid >> 4) << 3;      // 0..120
    const int tc = (tid & 15) << 3;      // 0..120
    const int aRow = tid >> 1;           // 0..127
    const int aCol = (tid & 1) << 3;     // 0 or 8
    const int bRow = tid >> 4;           // 0..15
    const int bCol = (tid & 15) << 2;    // 0..60

    const float* Ap = A + (long)(bm + aRow) * K + aCol;
    const float* Wp = W + (long)bRow * N + bn + bCol;

    float acc[8][8] = {};

    const int nIter = K >> 4;
    for (int it = 0; it < nIter; it++) {
        float4 a0 = *(const float4*)Ap;
        float4 a1 = *(const float4*)(Ap + 4);
        float4 b0 = *(const float4*)Wp;
        float4 b1 = *(const float4*)(Wp + 64);

        As[aCol + 0][aRow] = a0.x; As[aCol + 1][aRow] = a0.y;
        As[aCol + 2][aRow] = a0.z; As[aCol + 3][aRow] = a0.w;
        As[aCol + 4][aRow] = a1.x; As[aCol + 5][aRow] = a1.y;
        As[aCol + 6][aRow] = a1.z; As[aCol + 7][aRow] = a1.w;
        *(float4*)&Bs[bRow][bCol]      = b0;
        *(float4*)&Bs[bRow][bCol + 64] = b1;
        __syncthreads();

        #pragma unroll
        for (int kk = 0; kk < 16; kk++) {
            float av[8], bv[8];
            *(float4*)(av)     = *(const float4*)&As[kk][tr];
            *(float4*)(av + 4) = *(const float4*)&As[kk][tr + 4];
            *(float4*)(bv)     = *(const float4*)&Bs[kk][tc];
            *(float4*)(bv + 4) = *(const float4*)&Bs[kk][tc + 4];
            #pragma unroll
            for (int i = 0; i < 8; i++)
                #pragma unroll
                for (int j = 0; j < 8; j++)
                    acc[i][j] = fmaf(av[i], bv[j], acc[i][j]);
        }
        __syncthreads();

        Ap += 16;
        Wp += (long)16 * N;
    }

    #pragma unroll
    for (int i = 0; i < 8; i++) {
        const int row = bm + tr + i;
        #pragma unroll
        for (int j = 0; j < 8; j += 4) {
            const int col = bn + tc + j;
            float4 bz = *(const float4*)(bias + col);
            float4 r;
            r.x = acc[i][j + 0] + bz.x;
            r.y = acc[i][j + 1] + bz.y;
            r.z = acc[i][j + 2] + bz.z;
            r.w = acc[i][j + 3] + bz.w;
            if (RESID) {
                float4 rv = *(const float4*)(R + (long)row * N + col);
                r.x += rv.x; r.y += rv.y; r.z += rv.z; r.w += rv.w;
            }
            if (GELU) {
                r.x = fast_gelu(r.x); r.y = fast_gelu(r.y);
                r.z = fast_gelu(r.z); r.w = fast_gelu(r.w);
            }
            *(float4*)(C + (long)row * N + col) = r;
        }
    }
}

// ---------------------------------------------------------------- RoPE table
// CONJUGATE rotation (MEASURED correct in R15): sin table negated.
__global__ __launch_bounds__(256) void rope_table_kernel()
{
    const int i = blockIdx.x * 256 + threadIdx.x;   // 0 .. SLEN*16-1
    const int s = i >> 4;
    const int d = i & 15;
    const float inv = 1.0f / powf(10000.0f, (float)d * 2.0f / 32.0f);
    float cs, sn;
    sincosf((float)s * inv, &cs, &sn);
    g_cos[i] = cs;
    g_sin[i] = -sn;          // conjugate — DO NOT revert (R15 pass evidence)
}

// ---------------------------------------------------------------- RoPE apply (literal)
__global__ __launch_bounds__(256) void rope_apply_kernel(
    const float* __restrict__ qkv, float* __restrict__ Q, float* __restrict__ K)
{
    const long i = (long)blockIdx.x * 256 + threadIdx.x;   // 0 .. TOK*HID
    const int  t = (int)(i / HID);
    const int  c = (int)(i % HID);
    const int  h = c / HD;
    const int  d = c % HD;
    const int  s = t % SLEN;

    const float* qp = qkv + (long)t * HID3 + h * HD;
    const float* kp = qp + HID;

    float qv, kv;
    if (d < ROT_HALF) {
        const float cs = g_cos[s * ROT_HALF + d];
        const float sn = g_sin[s * ROT_HALF + d];
        qv = qp[d] * cs - qp[d + ROT_HALF] * sn;
        kv = kp[d] * cs - kp[d + ROT_HALF] * sn;
    } else if (d < 2 * ROT_HALF) {
        const int dd = d - ROT_HALF;
        const float cs = g_cos[s * ROT_HALF + dd];
        const float sn = g_sin[s * ROT_HALF + dd];
        qv = qp[dd] * sn + qp[d] * cs;
        kv = kp[dd] * sn + kp[d] * cs;
    } else {
        qv = qp[d];
        kv = kp[d];
    }
    Q[i] = qv;
    K[i] = kv;
}

// ---------------------------------------------------------------- Flash attention
// Causal, fp32. One WARP per query row (8 rows / 256-thread block). K/V tiles
// of 64 rows staged in smem shared by the 8 warps. Q from g_q, K from g_k
// (both pre-rotated, stride HID), V from g_qkv (stride HID3). Causality is
// the loop bound k <= q. Same function as the R15-passing dense path.
#define FB_ROWS 8
#define FB_KT   64

__global__ __launch_bounds__(256) void flash_kernel(
    const float* __restrict__ Q, const float* __restrict__ Kb,
    const float* __restrict__ qkv, float* __restrict__ outp)
{
    __shared__ float Ks[FB_KT][HD];   // 20 KB
    __shared__ float Vs[FB_KT][HD];   // 20 KB

    const int qg0  = blockIdx.x * FB_ROWS;
    const int h    = blockIdx.y;
    const int b    = blockIdx.z;
    const int tid  = threadIdx.x;
    const int warp = tid >> 5;
    const int lane = tid & 31;
    const int myq  = qg0 + warp;
    const float scale = 0.11180339887498948f;  // 1/sqrt(80)

    // This warp's rotated query row.
    const float* qrow = Q + (long)(b * SLEN + myq) * HID + h * HD;
    const float q0 = qrow[lane];
    const float q1 = qrow[lane + 32];
    const float q2 = (lane < 16) ? qrow[lane + 64] : 0.f;

    float m = -1e30f, l = 0.f, o0 = 0.f, o1 = 0.f, o2 = 0.f;

    const int ntiles = (qg0 + FB_ROWS - 1) / FB_KT + 1;

    for (int kt = 0; kt < ntiles; kt++) {
        const int k0 = kt * FB_KT;
        __syncthreads();   // previous tile fully consumed
        {
            const float* kb = Kb  + (long)(b * SLEN + k0) * HID  + h * HD;
            const float* vb = qkv + (long)(b * SLEN + k0) * HID3 + 2 * HID + h * HD;
            for (int i = tid; i < FB_KT * (HD / 4); i += 256) {
                const int r  = i / (HD / 4);
                const int c4 = (i % (HD / 4)) * 4;
                *(float4*)&Ks[r][c4] = *(const float4*)(kb + (long)r * HID  + c4);
                *(float4*)&Vs[r][c4] = *(const float4*)(vb + (long)r * HID3 + c4);
            }
        }
        __syncthreads();

        const int kmax = min(FB_KT, myq - k0 + 1);
        for (int j = 0; j < kmax; j++) {
            float part = q0 * Ks[j][lane] + q1 * Ks[j][lane + 32];
            if (lane < 16) part += q2 * Ks[j][lane + 64];
            #pragma unroll
            for (int w = 16; w > 0; w >>= 1)
                part += __shfl_xor_sync(0xffffffffu, part, w);

            const float sc   = part * scale;
            const float mnew = fmaxf(m, sc);
            const float corr = __expf(m - mnew);
            const float p    = __expf(sc - mnew);
            l  = l  * corr + p;
            o0 = o0 * corr + p * Vs[j][lane];
            o1 = o1 * corr + p * Vs[j][lane + 32];
            if (lane < 16) o2 = o2 * corr + p * Vs[j][lane + 64];
            m = mnew;
        }
    }

    const float linv = 1.0f / l;
    float* orow = outp + (long)(b * SLEN + myq) * HID + h * HD;
    orow[lane]      = o0 * linv;
    orow[lane + 32] = o1 * linv;
    if (lane < 16) orow[lane + 64] = o2 * linv;
}

// ---------------------------------------------------------------- launch
// Input mapping: dict order (MEASURED, R10+R12). out_weight: normal
// orientation (MEASURED, R10). RoPE: conjugate (MEASURED, R15 pass).
extern "C" void kernel_launch(void* const* d_in, const int* in_sizes, int n_in,
                              void* d_out, int out_size)
{
    (void)in_sizes; (void)n_in; (void)out_size;
    const float* hidden = (const float*)d_in[0];
    const float* ln_w   = (const float*)d_in[1];
    const float* ln_b   = (const float*)d_in[2];
    const float* qkv_w  = (const float*)d_in[3];
    const float* qkv_b  = (const float*)d_in[4];
    const float* out_w  = (const float*)d_in[5];
    const float* out_b  = (const float*)d_in[6];
    const float* fc1_w  = (const float*)d_in[7];
    const float* fc1_b  = (const float*)d_in[8];
    const float* fc2_w  = (const float*)d_in[9];
    const float* fc2_b  = (const float*)d_in[10];
    float* out = (float*)d_out;

    float *p_ln, *p_qkv, *p_attn, *p_fc1, *p_q, *p_k;
    cudaGetSymbolAddress((void**)&p_ln,   g_ln);
    cudaGetSymbolAddress((void**)&p_qkv,  g_qkv);
    cudaGetSymbolAddress((void**)&p_attn, g_attn);
    cudaGetSymbolAddress((void**)&p_fc1,  g_fc1);
    cudaGetSymbolAddress((void**)&p_q,    g_q);
    cudaGetSymbolAddress((void**)&p_k,    g_k);

    // 1. LayerNorm
    ln_simple_kernel<<<TOK / 8, 256>>>(hidden, ln_w, ln_b, p_ln);

    // 2. QKV projection: [4096,2560] @ [2560,7680] + b
    sgemm_kernel<false, false><<<dim3(HID3 / 128, TOK / 128), 256>>>(
        p_ln, qkv_w, qkv_b, nullptr, p_qkv, TOK, HID3, HID);

    // 3. rope table (conjugate) + rope application into g_q/g_k
    rope_table_kernel<<<(SLEN * ROT_HALF) / 256, 256>>>();
    rope_apply_kernel<<<(TOK * HID) / 256, 256>>>(p_qkv, p_q, p_k);

    // 4. causal flash attention -> g_attn
    flash_kernel<<<dim3(SLEN / FB_ROWS, NHEAD, 2), 256>>>(p_q, p_k, p_qkv, p_attn);

    // 5. out projection + residual(hidden) -> d_out
    sgemm_kernel<false, true><<<dim3(HID / 128, TOK / 128), 256>>>(
        p_attn, out_w, out_b, hidden, out, TOK, HID, HID);

    // 6. FC1 + GELU -> g_fc1
    sgemm_kernel<true, false><<<dim3(HID4 / 128, TOK / 128), 256>>>(
        p_ln, fc1_w, fc1_b, nullptr, p_fc1, TOK, HID4, HID);

    // 7. FC2 + residual(d_out) -> d_out (element-owned read+write)
    sgemm_kernel<false, true><<<dim3(HID / 128, TOK / 128), 256>>>(
        p_fc1, fc2_w, fc2_b, out, out, TOK, HID, HID4);
}